// round 9
// baseline (speedup 1.0000x reference)
#include <cuda_runtime.h>

// QuantumRegression: 12-wire state-vector sim, two samples per block packed
// into f32x2 lanes. State = 4096 x ulonglong2 (X=f32x2, Y=f32x2) = 64KB in
// shared. Storage index sw(a) = a ^ ((a>>4)&0xF) ^ ((a>>8)&0xF) (both upper
// nibbles folded into the low nibble) -- conflict-free for ALL pass layouts
// at 16B granularity, since each layout places the lane nibble j in exactly
// one nibble of a.
//
// Thread->amp maps are chosen so consecutive passes exchange data within a
// HALF-WARP (group of 16 lanes sharing one fixed nibble), making half the
// inter-pass syncs warp-local (__syncwarp) instead of block-wide. Phases:
//   P1 {A1,B1} fix bits3-0=G | P2 {C1,A2} fix bits7-4=G |
//   P3 {B2,C2} fix bits11-8=G | P4 {A3,B3} fix bits3-0=G | P5 {C3}
// -> 4 block barriers + 4 warp syncs (was 8 block barriers). Warps run
// staggered, spreading LDS bursts under other warps' FMA work.
//
// Circuit algebra (re-derived for the new maps):
//  - Layer 0 folded into closed-form product-state init (prefix parity).
//  - Per layer: window rotations (pure RX), deferred RZ diagonal (16-entry
//    batch-shared table), in-window staircase tau4 at store.
//  - Boundary CNOT(3,4): store-side fold at B-pass: index tau4(k^8c) =
//    tau4(k)^0xF*c, c = amp bit8 = (B1,B3: t0 | B2: t4). Base XOR 0xFF.
//  - Boundary CNOT(7,8): store-side fold at C-pass: c = amp bit4 =
//    (C1,C3: t4 | C2: t0). Base XOR 0xF. (C3: folded into measure index.)
//  - RZ global phase dropped; last layer = pure RX; <Z>@head_w fused.

typedef unsigned long long u64;

#define NW 12

// ---- packed f32x2 helpers ----
static __device__ __forceinline__ u64 pack2(float lo, float hi) {
    u64 r; asm("mov.b64 %0, {%1, %2};" : "=l"(r) : "f"(lo), "f"(hi)); return r;
}
static __device__ __forceinline__ float2 unpack2(u64 v) {
    float2 r; asm("mov.b64 {%0, %1}, %2;" : "=f"(r.x), "=f"(r.y) : "l"(v)); return r;
}
static __device__ __forceinline__ u64 dup2(float v) { return pack2(v, v); }
static __device__ __forceinline__ u64 fma2(u64 a, u64 b, u64 c) {
    u64 d; asm("fma.rn.f32x2 %0, %1, %2, %3;" : "=l"(d) : "l"(a), "l"(b), "l"(c)); return d;
}
static __device__ __forceinline__ u64 mul2(u64 a, u64 b) {
    u64 d; asm("mul.rn.f32x2 %0, %1, %2;" : "=l"(d) : "l"(a), "l"(b)); return d;
}
static __device__ __forceinline__ u64 neg2(u64 a) { return a ^ 0x8000000080000000ULL; }

// staircase CNOT permutation on 4 bits (GF2-linear, tau4(8)=0xF)
__device__ __host__ __forceinline__ constexpr int tau4(int k) {
    int b3 = (k >> 3) & 1;
    int b2 = ((k >> 2) & 1) ^ b3;
    int b1 = ((k >> 1) & 1) ^ b2;
    int b0 = (k & 1) ^ b1;
    return (b3 << 3) | (b2 << 2) | (b1 << 1) | b0;
}

// ---- shared memory layout (bytes) ----
#define SM_ST   0        // ulonglong2 st[4096]            : 65536
#define SM_G    65536    // ulonglong2 gx[3*12] (c,s)      : 576
#define SM_D    66112    // ulonglong2 dtab[2*3*16]        : 1536  (L1,L2 diag)
#define SM_V    67648    // ulonglong2 v[12][2]            : 384
#define SM_F    68032    // ulonglong2 F[16]               : 256
#define SM_HW   68288    // float hw[12]                   : 48
#define SM_WK   68336    // float wk[16]                   : 64
#define SM_RED  68400    // float2 red[8]                  : 64
#define SMEM_BYTES 68464

// ---- RX gate bundle ----
struct GX { u64 c, s, ns; };
static __device__ __forceinline__ GX load_gx(const ulonglong2* __restrict__ g) {
    GX r; ulonglong2 p = g[0]; r.c = p.x; r.s = p.y; r.ns = neg2(p.y); return r;
}

// one pure RX rotation on pair (i0, i1)
static __device__ __forceinline__ void rxp(const GX& G, u64* X, u64* Y, int i0, int i1) {
    u64 X0 = X[i0], Y0 = Y[i0], X1 = X[i1], Y1 = Y[i1];
    X[i0] = fma2(G.c, X0, mul2(G.s, Y1));
    Y[i0] = fma2(G.c, Y0, mul2(G.ns, X1));
    X[i1] = fma2(G.c, X1, mul2(G.s, Y0));
    Y[i1] = fma2(G.c, Y1, mul2(G.ns, X0));
}

// apply window diagonal D[k] (unit phase, batch-shared)
static __device__ __forceinline__ void diagp(const ulonglong2* __restrict__ dt,
                                             u64* X, u64* Y, int k) {
    ulonglong2 d = dt[k];
    u64 nx = fma2(d.x, X[k], neg2(mul2(d.y, Y[k])));
    u64 ny = fma2(d.x, Y[k], mul2(d.y, X[k]));
    X[k] = nx; Y[k] = ny;
}

// sw-image of the k nibble at nibble position NP (compile-time XOR constants)
template<int NP>
__device__ __forceinline__ int offk(int k) {
    if (NP == 2)      return (k << 8) ^ k;
    else if (NP == 1) return (k << 4) ^ k;
    else              return k;
}

// One pass: load, 4 RX rotations, epilogue per MODE.
//  MODE 0: diag + tau4-permuted store (layers 1,2)
//  MODE 1: tau4-permuted store, no diag (layer 3, A/B)
//  MODE 2: fused measurement (layer 3, C)
// CNOT folds are pre-XORed into storeBase (or wkxor for MODE 2).
template<int NP, int MODE>
__device__ __forceinline__ void do_pass(ulonglong2* __restrict__ st,
                                        const ulonglong2* __restrict__ g,
                                        const ulonglong2* __restrict__ dt,
                                        int loadBase, int storeBase,
                                        float whigh, const float* __restrict__ wk,
                                        int wkxor, float* pacc)
{
    u64 X[16], Y[16];
    GX G0 = load_gx(g);
#pragma unroll
    for (int k = 0; k < 8; k++) {              // load pair + first rotation
        ulonglong2 a = st[loadBase ^ offk<NP>(k)];
        ulonglong2 b = st[loadBase ^ offk<NP>(k | 8)];
        X[k] = a.x; Y[k] = a.y; X[k | 8] = b.x; Y[k | 8] = b.y;
        rxp(G0, X, Y, k, k | 8);
    }
    GX G1 = load_gx(g + 1);
#pragma unroll
    for (int k = 0; k < 16; k++) if (!(k & 4)) rxp(G1, X, Y, k, k | 4);
    GX G2 = load_gx(g + 2);
#pragma unroll
    for (int k = 0; k < 16; k++) if (!(k & 2)) rxp(G2, X, Y, k, k | 2);
    GX G3 = load_gx(g + 3);
#pragma unroll
    for (int k = 0; k < 16; k += 2) {          // last rotation + epilogue
        rxp(G3, X, Y, k, k | 1);
        if constexpr (MODE == 2) {
            int i0 = tau4(k) ^ wkxor;
            float wl = whigh + wk[i0];
            u64 U = fma2(X[k], X[k], mul2(Y[k], Y[k]));
            float2 u = unpack2(U);
            pacc[0] = fmaf(u.x, wl, pacc[0]);
            pacc[1] = fmaf(u.y, wl, pacc[1]);
            int i1 = tau4(k | 1) ^ wkxor;
            wl = whigh + wk[i1];
            U = fma2(X[k | 1], X[k | 1], mul2(Y[k | 1], Y[k | 1]));
            u = unpack2(U);
            pacc[0] = fmaf(u.x, wl, pacc[0]);
            pacc[1] = fmaf(u.y, wl, pacc[1]);
        } else {
            if constexpr (MODE == 0) { diagp(dt, X, Y, k); diagp(dt, X, Y, k | 1); }
            ulonglong2 v0; v0.x = X[k];     v0.y = Y[k];
            st[storeBase ^ offk<NP>(tau4(k))] = v0;
            ulonglong2 v1; v1.x = X[k | 1]; v1.y = Y[k | 1];
            st[storeBase ^ offk<NP>(tau4(k | 1))] = v1;
        }
    }
}

__global__ void __launch_bounds__(256, 2)
qsim5_kernel(const float* __restrict__ inputs,
             const float* __restrict__ params,
             const float* __restrict__ head_w,
             const float* __restrict__ head_b,
             float* __restrict__ out)
{
    extern __shared__ char sm[];
    ulonglong2* st   = (ulonglong2*)(sm + SM_ST);
    ulonglong2* gx   = (ulonglong2*)(sm + SM_G);
    ulonglong2* dtab = (ulonglong2*)(sm + SM_D);
    ulonglong2* vtab = (ulonglong2*)(sm + SM_V);
    ulonglong2* Ftab = (ulonglong2*)(sm + SM_F);
    float* hw  = (float*)(sm + SM_HW);
    float* wk  = (float*)(sm + SM_WK);
    float2* red = (float2*)(sm + SM_RED);

    const int b = blockIdx.x;
    const int t = threadIdx.x;

    // ---- phase 1: RX gates, diagonal tables, layer-0 vectors, weights ----
    if (t < 36) {                      // RX coeffs: layer 1+t/12, wire t%12
        float th = params[12 + t];
        float c, s; sincosf(0.5f * th, &s, &c);
        ulonglong2 e; e.x = dup2(c); e.y = dup2(s);
        gx[t] = e;
    }
    if (t >= 64 && t < 160) {          // diag tables: D[m] = e^{i sum th_w bit_w}
        int i = t - 64;                // layer = i/48 (0->L1), window = (i%48)/16, m = i&15
        int l = i / 48, p = (i % 48) / 16, m = i & 15;
        const float* th = params + (l + 1) * NW + 4 * p;
        float phi = 0.f;
#pragma unroll
        for (int q = 0; q < 4; q++)
            if ((m >> (3 - q)) & 1) phi += th[q];
        float cp, sp; sincosf(phi, &sp, &cp);
        ulonglong2 e; e.x = dup2(cp); e.y = dup2(sp);
        dtab[i] = e;
    }
    if (t < NW) {                      // layer-0 per-wire 2-vectors (both samples)
        int w = t;
        float th = params[w];
        float c0, s0; sincosf(0.5f * th, &s0, &c0);
        float cn = c0 * c0 - s0 * s0, sn = 2.f * s0 * c0;
        float v0x[2], v0y[2], v1x[2], v1y[2];
#pragma unroll
        for (int jj = 0; jj < 2; jj++) {
            float cy, sy; sincosf(0.5f * inputs[(2 * b + jj) * NW + w], &sy, &cy);
            v0x[jj] = c0 * cy;  v0y[jj] = -s0 * sy;
            float zx = c0 * sy, zy = -s0 * cy;           // z = -i s cy + c sy
            v1x[jj] = cn * zx - sn * zy;                  // e^{i th} * z
            v1y[jj] = sn * zx + cn * zy;
        }
        ulonglong2 e0; e0.x = pack2(v0x[0], v0x[1]); e0.y = pack2(v0y[0], v0y[1]);
        ulonglong2 e1; e1.x = pack2(v1x[0], v1x[1]); e1.y = pack2(v1y[0], v1y[1]);
        vtab[(w << 1) | 0] = e0;
        vtab[(w << 1) | 1] = e1;
        hw[w] = head_w[w];
    }
    if (t < 16) {                      // measurement weights for wires 8..11
        float w8 = head_w[8], w9 = head_w[9], w10 = head_w[10], w11 = head_w[11];
        wk[t] = ((t & 8) ? -w8 : w8) + ((t & 4) ? -w9 : w9)
              + ((t & 2) ? -w10 : w10) + ((t & 1) ? -w11 : w11);
    }
    __syncthreads();

    // ---- phase 2: F table (wires 0..3 staircase products) ----
    if (t < 16) {
        int c0 = (t >> 3) & 1, c1 = (t >> 2) & 1, c2 = (t >> 1) & 1, c3 = t & 1;
        int b0 = c0, b1 = c1 ^ c0, b2 = c2 ^ c1, b3 = c3 ^ c2;
        ulonglong2 a = vtab[0 | b0];
        u64 PX = a.x, PY = a.y;
        int bb[3] = {b1, b2, b3};
#pragma unroll
        for (int w = 1; w <= 3; w++) {
            ulonglong2 q = vtab[(w << 1) | bb[w - 1]];
            u64 nx = fma2(PX, q.x, neg2(mul2(PY, q.y)));
            u64 ny = fma2(PX, q.y, mul2(PY, q.x));
            PX = nx; PY = ny;
        }
        ulonglong2 f; f.x = PX; f.y = PY; Ftab[t] = f;
    }

    // ---- per-thread bases: sw(a) = a ^ nib1(a) ^ nib2(a) folded into nib0 ----
    const int jn = t & 15, Gg = t >> 4;
    const int baseA1 = ((jn << 4) | Gg) ^ jn;            // map [k|j|G]
    const int baseB1 = ((jn << 8) | Gg) ^ jn;            // map [j|k|G]
    const int baseC1 = ((jn << 8) | (Gg << 4)) ^ jn ^ Gg;// map [j|G|k]
    const int baseA2 = t ^ Gg;                           // map [k|G|j]
    const int baseB2 = ((Gg << 8) | jn) ^ Gg;            // map [G|k|j]
    const int baseC2 = ((Gg << 8) | (jn << 4)) ^ jn ^ Gg;// map [G|j|k]
    // CNOT store-base folds (control bit per map; offk images of 0xF)
    const int stB1 = baseB1 ^ ((t & 1) ? 0xFF : 0);          // C34, c=bit8=t0
    const int stC1 = baseC1 ^ (((t >> 4) & 1) ? 0xF : 0);    // C78, c=bit4=t4
    const int stB2 = baseB2 ^ (((t >> 4) & 1) ? 0xFF : 0);   // C34(L2), c=bit8=t4
    const int stC2 = baseC2 ^ ((t & 1) ? 0xF : 0);           // C78(L2), c=bit4=t0
    const int wkxor = ((t >> 4) & 1) ? 0xF : 0;              // C78(L3) at measure

    // measurement weight for amp bits 11..4 in C3 map [j|G|k]:
    // wire i (0-3) sign <- t bit (3-i); wire i (4-7) sign <- t bit (11-i)
    float whigh = 0.f;
#pragma unroll
    for (int m = 0; m < 4; m++) {
        float w = hw[3 - m];
        whigh += ((t >> m) & 1) ? -w : w;
    }
#pragma unroll
    for (int m = 4; m < 8; m++) {
        float w = hw[11 - m];
        whigh += ((t >> m) & 1) ? -w : w;
    }
    __syncthreads();

    float pacc[2] = {0.f, 0.f};
    const ulonglong2* g1 = gx;            // layer 1 gates (wires 0..11)
    const ulonglong2* g2 = gx + 12;       // layer 2
    const ulonglong2* g3 = gx + 24;       // layer 3
    const ulonglong2* d1 = dtab;          // layer-1 diagonals (A,B,C x 16)
    const ulonglong2* d2 = dtab + 48;     // layer-2 diagonals

    // ======== P1: A1 (init + rot w0-3 + diag + stair store), warp-local ====
    {
        u64 X[16], Y[16];
        // prefix-parity bits for wires 5..11 from (j,G):
        int b5 = ((t >> 2) ^ (t >> 3)) & 1, b6 = ((t >> 1) ^ (t >> 2)) & 1;
        int b7 = (t ^ (t >> 1)) & 1,        b8 = ((t >> 7) ^ t) & 1;
        int b9 = ((t >> 6) ^ (t >> 7)) & 1, b10 = ((t >> 5) ^ (t >> 6)) & 1;
        int b11 = ((t >> 4) ^ (t >> 5)) & 1;
        ulonglong2 q5 = vtab[(5 << 1) | b5];
        u64 PX = q5.x, PY = q5.y;
        int bbv[6] = {b6, b7, b8, b9, b10, b11};
#pragma unroll
        for (int w = 6; w <= 11; w++) {
            ulonglong2 q = vtab[(w << 1) | bbv[w - 6]];
            u64 nx = fma2(PX, q.x, neg2(mul2(PY, q.y)));
            u64 ny = fma2(PX, q.y, mul2(PY, q.x));
            PX = nx; PY = ny;
        }
        int j3 = (t >> 3) & 1;             // wire-4 parity seed
        ulonglong2 q0 = vtab[(4 << 1) | j3];
        ulonglong2 q1 = vtab[(4 << 1) | (j3 ^ 1)];
        u64 R0X = fma2(PX, q0.x, neg2(mul2(PY, q0.y)));
        u64 R0Y = fma2(PX, q0.y, mul2(PY, q0.x));
        u64 R1X = fma2(PX, q1.x, neg2(mul2(PY, q1.y)));
        u64 R1Y = fma2(PX, q1.y, mul2(PY, q1.x));
        GX G0 = load_gx(g1);
#pragma unroll
        for (int k = 0; k < 8; k++) {      // build pair (k, k|8), rotate wire0
            ulonglong2 Fk0 = Ftab[k];
            u64 QX = (k & 1) ? R1X : R0X;  // amp bit8 = k0 selects v4 branch
            u64 QY = (k & 1) ? R1Y : R0Y;
            X[k] = fma2(Fk0.x, QX, neg2(mul2(Fk0.y, QY)));
            Y[k] = fma2(Fk0.x, QY, mul2(Fk0.y, QX));
            ulonglong2 Fk1 = Ftab[k | 8];
            X[k | 8] = fma2(Fk1.x, QX, neg2(mul2(Fk1.y, QY)));
            Y[k | 8] = fma2(Fk1.x, QY, mul2(Fk1.y, QX));
            rxp(G0, X, Y, k, k | 8);
        }
        GX G1 = load_gx(g1 + 1);
#pragma unroll
        for (int k = 0; k < 16; k++) if (!(k & 4)) rxp(G1, X, Y, k, k | 4);
        GX G2 = load_gx(g1 + 2);
#pragma unroll
        for (int k = 0; k < 16; k++) if (!(k & 2)) rxp(G2, X, Y, k, k | 2);
        GX G3 = load_gx(g1 + 3);
#pragma unroll
        for (int k = 0; k < 16; k += 2) {  // last rotation + diag + store
            rxp(G3, X, Y, k, k | 1);
            diagp(d1, X, Y, k); diagp(d1, X, Y, k | 1);
            ulonglong2 v0; v0.x = X[k];     v0.y = Y[k];
            st[baseA1 ^ offk<2>(tau4(k))] = v0;
            ulonglong2 v1; v1.x = X[k | 1]; v1.y = Y[k | 1];
            st[baseA1 ^ offk<2>(tau4(k | 1))] = v1;
        }
    }
    __syncwarp();
    do_pass<1, 0>(st, g1 + 4, d1 + 16, baseB1, stB1, whigh, wk, 0, pacc);  // B1
    __syncthreads();
    // ======== P2 ========
    do_pass<0, 0>(st, g1 + 8, d1 + 32, baseC1, stC1, whigh, wk, 0, pacc);  // C1
    __syncwarp();
    do_pass<2, 0>(st, g2,     d2,      baseA2, baseA2, whigh, wk, 0, pacc);// A2
    __syncthreads();
    // ======== P3 ========
    do_pass<1, 0>(st, g2 + 4, d2 + 16, baseB2, stB2, whigh, wk, 0, pacc);  // B2
    __syncwarp();
    do_pass<0, 0>(st, g2 + 8, d2 + 32, baseC2, stC2, whigh, wk, 0, pacc);  // C2
    __syncthreads();
    // ======== P4 (layer 3, pure RX) ========
    do_pass<2, 1>(st, g3,     nullptr, baseA1, baseA1, whigh, wk, 0, pacc);// A3
    __syncwarp();
    do_pass<1, 1>(st, g3 + 4, nullptr, baseB1, stB1, whigh, wk, 0, pacc);  // B3
    __syncthreads();
    // ======== P5: C3 + fused measurement ========
    do_pass<0, 2>(st, g3 + 8, nullptr, baseC1, 0, whigh, wk, wkxor, pacc);

    // ---- reduce both samples ----
    float p0 = pacc[0], p1 = pacc[1];
#pragma unroll
    for (int o = 16; o; o >>= 1) {
        p0 += __shfl_xor_sync(0xFFFFFFFFu, p0, o);
        p1 += __shfl_xor_sync(0xFFFFFFFFu, p1, o);
    }
    if ((t & 31) == 0) red[t >> 5] = make_float2(p0, p1);
    __syncthreads();
    if (t < 2) {
        float s = 0.f;
#pragma unroll
        for (int w = 0; w < 8; w++) s += (t == 0) ? red[w].x : red[w].y;
        out[2 * b + t] = s + head_b[0];
    }
}

extern "C" void kernel_launch(void* const* d_in, const int* in_sizes, int n_in,
                              void* d_out, int out_size)
{
    const float* inputs = (const float*)d_in[0];
    const float* params = (const float*)d_in[1];
    const float* head_w = (const float*)d_in[2];
    const float* head_b = (const float*)d_in[3];
    float* out = (float*)d_out;

    cudaFuncSetAttribute(qsim5_kernel, cudaFuncAttributeMaxDynamicSharedMemorySize, SMEM_BYTES);
    int B2 = out_size / 2;   // two samples per block
    qsim5_kernel<<<B2, 256, SMEM_BYTES>>>(inputs, params, head_w, head_b, out);
}

// round 10
// speedup vs baseline: 1.1997x; 1.1997x over previous
#include <cuda_runtime.h>

// QuantumRegression: 12-wire state-vector sim, two samples per block packed
// into f32x2 lanes. State = 4096 x ulonglong2 (X=f32x2, Y=f32x2) = 64KB in
// shared, storage index sw(e) = e ^ ((e>>4)&7) (conflict-free for all pass
// layouts at 16B granularity, affine-in-k addressing per pass).  [R7 maps]
//
// Circuit structure (CNOT algebra identical to the verified R7 kernel):
//  - Layer 0 folded into closed-form product-state init (prefix parity).
//  - Layers 1..3: 3 passes of 4 rotated wires (0-3 / 4-7 / 8-11); boundary
//    CNOT(3,4) folded into pass-B store base, boundary CNOT(7,8) deferred
//    into next pass-A load base (conjugated: flip bits 3..0 iff bit4).
//  - RZ diagonals deferred: batch-shared 16-entry table per window.
//  - NEW (this round): TANGENT-FORM rotations. RX = c*(I - i tan X~), so a
//    rotation pair costs 4 f32x2 FMAs instead of 8. The dropped scalar c is
//    batch-shared: for layers 1-2 the window prod(c) folds into the diagonal
//    table (free); for layer 3 the whole-layer prod(c) is applied once as
//    alpha3^2 on the scalar output.
//  - RZ global phase dropped; last layer = pure RX; <Z>@head_w fused.

typedef unsigned long long u64;

#define NW 12

// ---- packed f32x2 helpers ----
static __device__ __forceinline__ u64 pack2(float lo, float hi) {
    u64 r; asm("mov.b64 %0, {%1, %2};" : "=l"(r) : "f"(lo), "f"(hi)); return r;
}
static __device__ __forceinline__ float2 unpack2(u64 v) {
    float2 r; asm("mov.b64 {%0, %1}, %2;" : "=f"(r.x), "=f"(r.y) : "l"(v)); return r;
}
static __device__ __forceinline__ u64 dup2(float v) { return pack2(v, v); }
static __device__ __forceinline__ u64 fma2(u64 a, u64 b, u64 c) {
    u64 d; asm("fma.rn.f32x2 %0, %1, %2, %3;" : "=l"(d) : "l"(a), "l"(b), "l"(c)); return d;
}
static __device__ __forceinline__ u64 mul2(u64 a, u64 b) {
    u64 d; asm("mul.rn.f32x2 %0, %1, %2;" : "=l"(d) : "l"(a), "l"(b)); return d;
}
static __device__ __forceinline__ u64 neg2(u64 a) { return a ^ 0x8000000080000000ULL; }

// staircase CNOT permutation on 4 bits (GF2-linear)
__device__ __host__ __forceinline__ constexpr int tau4(int k) {
    int b3 = (k >> 3) & 1;
    int b2 = ((k >> 2) & 1) ^ b3;
    int b1 = ((k >> 1) & 1) ^ b2;
    int b0 = (k & 1) ^ b1;
    return (b3 << 3) | (b2 << 2) | (b1 << 1) | b0;
}

// ---- shared memory layout (bytes) ----
#define SM_ST   0        // ulonglong2 st[4096]            : 65536
#define SM_G    65536    // ulonglong2 gx[3*12] (tn,-tn)   : 576
#define SM_D    66112    // ulonglong2 dtab[2*3*16]        : 1536  (L1,L2 diag*prodc)
#define SM_V    67648    // ulonglong2 v[12][2]            : 384
#define SM_F    68032    // ulonglong2 F[16]               : 256
#define SM_HW   68288    // float hw[12]                   : 48
#define SM_WK   68336    // float wk[16]                   : 64
#define SM_RED  68400    // float2 red[8]                  : 64
#define SM_A3   68464    // float alpha3sq                 : 4
#define SMEM_BYTES 68480

// ---- tangent-form RX gate bundle: one LDS.128 ----
struct GX { u64 tn, ntn; };
static __device__ __forceinline__ GX load_gx(const ulonglong2* __restrict__ g) {
    GX r; ulonglong2 p = g[0]; r.tn = p.x; r.ntn = p.y; return r;
}

// tangent-form RX rotation on pair (i0, i1): 4 FMAs (scale c deferred)
static __device__ __forceinline__ void rxp(const GX& G, u64* X, u64* Y, int i0, int i1) {
    u64 X0 = X[i0], Y0 = Y[i0], X1 = X[i1], Y1 = Y[i1];
    X[i0] = fma2(G.tn, Y1, X0);
    Y[i0] = fma2(G.ntn, X1, Y0);
    X[i1] = fma2(G.tn, Y0, X1);
    Y[i1] = fma2(G.ntn, X0, Y1);
}

// apply window diagonal D[k] (includes window prod(c); batch-shared)
static __device__ __forceinline__ void diagp(const ulonglong2* __restrict__ dt,
                                             u64* X, u64* Y, int k) {
    ulonglong2 d = dt[k];
    u64 nx = fma2(d.x, X[k], neg2(mul2(d.y, Y[k])));
    u64 ny = fma2(d.x, Y[k], mul2(d.y, X[k]));
    X[k] = nx; Y[k] = ny;
}

// Per-pass element address masks (applied to swizzled storage index).
template<int P>
__device__ __forceinline__ int addr_of(int base, int k) {
    if (P == 0)      return base + (k << 8);                  // immediate offsets
    else if (P == 1) return base ^ ((k << 4) | (k & 7));      // compile-time XOR mask
    else             return base ^ k;                         // compile-time XOR mask
}

// One pass: 4 tangent-RX rotations, then per MODE:
//  MODE 0: window diagonal dt + CNOT-permuted store   (layers 1,2)
//  MODE 1: CNOT-permuted store, no diagonal           (layer 3, passes A,B)
//  MODE 2: fused measurement, no diagonal             (layer 3, pass C)
template<int P, int MODE>
__device__ __forceinline__ void do_pass(ulonglong2* __restrict__ st,
                                        const ulonglong2* __restrict__ g,
                                        const ulonglong2* __restrict__ dt,
                                        int loadBase, int storeBase,
                                        float whigh, const float* __restrict__ wk,
                                        int wkxor, float* pacc)
{
    u64 X[16], Y[16];
    GX G0 = load_gx(g);
#pragma unroll
    for (int j = 0; j < 8; j++) {              // load pair + first rotation
        ulonglong2 a = st[addr_of<P>(loadBase, j)];
        ulonglong2 b = st[addr_of<P>(loadBase, j | 8)];
        X[j] = a.x; Y[j] = a.y; X[j | 8] = b.x; Y[j | 8] = b.y;
        rxp(G0, X, Y, j, j | 8);
    }
    GX G1 = load_gx(g + 1);
#pragma unroll
    for (int j = 0; j < 16; j++) if (!(j & 4)) rxp(G1, X, Y, j, j | 4);
    GX G2 = load_gx(g + 2);
#pragma unroll
    for (int j = 0; j < 16; j++) if (!(j & 2)) rxp(G2, X, Y, j, j | 2);
    GX G3 = load_gx(g + 3);
#pragma unroll
    for (int j = 0; j < 16; j += 2) {          // last rotation + epilogue
        rxp(G3, X, Y, j, j | 1);
        if constexpr (MODE == 2) {             // fused measurement
            int i0 = tau4(j) ^ wkxor;
            float wl = whigh + wk[i0];
            u64 U = fma2(X[j], X[j], mul2(Y[j], Y[j]));
            float2 u = unpack2(U);
            pacc[0] = fmaf(u.x, wl, pacc[0]);
            pacc[1] = fmaf(u.y, wl, pacc[1]);
            int i1 = tau4(j | 1) ^ wkxor;
            wl = whigh + wk[i1];
            U = fma2(X[j | 1], X[j | 1], mul2(Y[j | 1], Y[j | 1]));
            u = unpack2(U);
            pacc[0] = fmaf(u.x, wl, pacc[0]);
            pacc[1] = fmaf(u.y, wl, pacc[1]);
        } else {
            if constexpr (MODE == 0) { diagp(dt, X, Y, j); diagp(dt, X, Y, j | 1); }
            ulonglong2 v0; v0.x = X[j];     v0.y = Y[j];
            st[addr_of<P>(storeBase, tau4(j))] = v0;
            ulonglong2 v1; v1.x = X[j | 1]; v1.y = Y[j | 1];
            st[addr_of<P>(storeBase, tau4(j | 1))] = v1;
        }
    }
}

__global__ void __launch_bounds__(256, 2)
qsim6_kernel(const float* __restrict__ inputs,
             const float* __restrict__ params,
             const float* __restrict__ head_w,
             const float* __restrict__ head_b,
             float* __restrict__ out)
{
    extern __shared__ char sm[];
    ulonglong2* st   = (ulonglong2*)(sm + SM_ST);
    ulonglong2* gx   = (ulonglong2*)(sm + SM_G);
    ulonglong2* dtab = (ulonglong2*)(sm + SM_D);
    ulonglong2* vtab = (ulonglong2*)(sm + SM_V);
    ulonglong2* Ftab = (ulonglong2*)(sm + SM_F);
    float* hw  = (float*)(sm + SM_HW);
    float* wk  = (float*)(sm + SM_WK);
    float2* red = (float2*)(sm + SM_RED);
    float* a3  = (float*)(sm + SM_A3);

    const int b = blockIdx.x;
    const int t = threadIdx.x;

    // ---- phase 1: tangent gates, scaled diagonal tables, layer-0 vectors ----
    if (t < 36) {                      // tan coeffs: layer 1+t/12, wire t%12
        float th = params[12 + t];
        float c, s; sincosf(0.5f * th, &s, &c);
        float tn = s / c;
        ulonglong2 e; e.x = dup2(tn); e.y = dup2(-tn);
        gx[t] = e;
    }
    if (t == 40) {                     // layer-3 scalar: alpha3^2 = prod(c)^2
        float prod = 1.f;
#pragma unroll
        for (int w = 0; w < NW; w++) prod *= cosf(0.5f * params[36 + w]);
        a3[0] = prod * prod;
    }
    if (t >= 64 && t < 160) {          // diag tables: prod(c) * e^{i sum th_w bit_w}
        int i = t - 64;                // layer = i/48 (0->L1), window = (i%48)/16, m = i&15
        int l = i / 48, p = (i % 48) / 16, m = i & 15;
        const float* th = params + (l + 1) * NW + 4 * p;
        float phi = 0.f, cprod = 1.f;
#pragma unroll
        for (int q = 0; q < 4; q++) {
            if ((m >> (3 - q)) & 1) phi += th[q];
            cprod *= cosf(0.5f * th[q]);
        }
        float cp, sp; sincosf(phi, &sp, &cp);
        ulonglong2 e; e.x = dup2(cprod * cp); e.y = dup2(cprod * sp);
        dtab[i] = e;
    }
    if (t < NW) {                      // layer-0 per-wire 2-vectors (both samples)
        int w = t;
        float th = params[w];
        float c0, s0; sincosf(0.5f * th, &s0, &c0);
        float cn = c0 * c0 - s0 * s0, sn = 2.f * s0 * c0;
        float v0x[2], v0y[2], v1x[2], v1y[2];
#pragma unroll
        for (int j = 0; j < 2; j++) {
            float cy, sy; sincosf(0.5f * inputs[(2 * b + j) * NW + w], &sy, &cy);
            v0x[j] = c0 * cy;  v0y[j] = -s0 * sy;
            float zx = c0 * sy, zy = -s0 * cy;           // z = -i s cy + c sy
            v1x[j] = cn * zx - sn * zy;                   // e^{i th} * z
            v1y[j] = sn * zx + cn * zy;
        }
        ulonglong2 e0; e0.x = pack2(v0x[0], v0x[1]); e0.y = pack2(v0y[0], v0y[1]);
        ulonglong2 e1; e1.x = pack2(v1x[0], v1x[1]); e1.y = pack2(v1y[0], v1y[1]);
        vtab[(w << 1) | 0] = e0;
        vtab[(w << 1) | 1] = e1;
        hw[w] = head_w[w];
    }
    if (t < 16) {                      // measurement weights for wires 8..11
        float w8 = head_w[8], w9 = head_w[9], w10 = head_w[10], w11 = head_w[11];
        wk[t] = ((t & 8) ? -w8 : w8) + ((t & 4) ? -w9 : w9)
              + ((t & 2) ? -w10 : w10) + ((t & 1) ? -w11 : w11);
    }
    __syncthreads();

    // ---- phase 2: F table (wires 0..3 staircase products, per sample-pair) ----
    if (t < 16) {
        int c0 = (t >> 3) & 1, c1 = (t >> 2) & 1, c2 = (t >> 1) & 1, c3 = t & 1;
        int b0 = c0, b1 = c1 ^ c0, b2 = c2 ^ c1, b3 = c3 ^ c2;
        ulonglong2 a = vtab[0 | b0];
        u64 PX = a.x, PY = a.y;
        int bb[3] = {b1, b2, b3};
#pragma unroll
        for (int w = 1; w <= 3; w++) {
            ulonglong2 q = vtab[(w << 1) | bb[w - 1]];
            u64 nx = fma2(PX, q.x, neg2(mul2(PY, q.y)));
            u64 ny = fma2(PX, q.y, mul2(PY, q.x));
            PX = nx; PY = ny;
        }
        ulonglong2 f; f.x = PX; f.y = PY; Ftab[t] = f;
    }

    // per-thread bases (R7 maps, verified)
    const int baseA  = t ^ ((t >> 4) & 7);              // pass-A canonical base
    const int tA2    = t ^ (((t >> 4) & 1) * 0xF);      // conjugated C78 deferral
    const int baseA2 = tA2 ^ ((tA2 >> 4) & 7);          // pass-A load base (L2,L3)
    const int baseB  = ((t >> 4) << 8) | (t & 15);
    const int baseBs = baseB ^ (((t >> 4) & 1) ? 0xF7 : 0);  // CNOT(3,4) fold
    const int baseC  = (t << 4) | (t & 7);
    const int wkxor  = (t & 1) ? 0xF : 0;               // CNOT(7,8) fold at measure

    // measurement weight for wires 0..7 (t bits 7..0, wire i <-> t bit 7-i)
    float whigh = 0.f;
#pragma unroll
    for (int m = 0; m < 8; m++) {
        float w = hw[7 - m];
        whigh += ((t >> m) & 1) ? -w : w;
    }
    __syncthreads();

    float pacc[2] = {0.f, 0.f};
    const ulonglong2* g1 = gx;            // layer 1 (12 gates)
    const ulonglong2* g2 = gx + 12;       // layer 2
    const ulonglong2* g3 = gx + 24;       // layer 3
    const ulonglong2* d1 = dtab;          // layer-1 diagonals (3 windows x 16)
    const ulonglong2* d2 = dtab + 48;     // layer-2 diagonals

    // ======== Layer 1, pass A: closed-form init + tan-rx chain + diag ====
    {
        u64 X[16], Y[16];
        int u = t ^ (t >> 1);             // u bit (11-w) = b_w for wires 5..11
        ulonglong2 p5 = vtab[(5 << 1) | ((u >> 6) & 1)];
        u64 PX = p5.x, PY = p5.y;
#pragma unroll
        for (int w = 6; w <= 11; w++) {
            ulonglong2 q = vtab[(w << 1) | ((u >> (11 - w)) & 1)];
            u64 nx = fma2(PX, q.x, neg2(mul2(PY, q.y)));
            u64 ny = fma2(PX, q.y, mul2(PY, q.x));
            PX = nx; PY = ny;
        }
        int t7 = (t >> 7) & 1;
        ulonglong2 q0 = vtab[(4 << 1) | t7];
        ulonglong2 q1 = vtab[(4 << 1) | (t7 ^ 1)];
        u64 R0X = fma2(PX, q0.x, neg2(mul2(PY, q0.y)));
        u64 R0Y = fma2(PX, q0.y, mul2(PY, q0.x));
        u64 R1X = fma2(PX, q1.x, neg2(mul2(PY, q1.y)));
        u64 R1Y = fma2(PX, q1.y, mul2(PY, q1.x));
        GX G0 = load_gx(g1);
#pragma unroll
        for (int j = 0; j < 8; j++) {     // build pair (j, j|8) then rotate it
            ulonglong2 Fk0 = Ftab[j];
            u64 QX = (j & 1) ? R1X : R0X;
            u64 QY = (j & 1) ? R1Y : R0Y;
            X[j] = fma2(Fk0.x, QX, neg2(mul2(Fk0.y, QY)));
            Y[j] = fma2(Fk0.x, QY, mul2(Fk0.y, QX));
            ulonglong2 Fk1 = Ftab[j | 8];
            X[j | 8] = fma2(Fk1.x, QX, neg2(mul2(Fk1.y, QY)));
            Y[j | 8] = fma2(Fk1.x, QY, mul2(Fk1.y, QX));
            rxp(G0, X, Y, j, j | 8);
        }
        GX G1 = load_gx(g1 + 1);
#pragma unroll
        for (int j = 0; j < 16; j++) if (!(j & 4)) rxp(G1, X, Y, j, j | 4);
        GX G2 = load_gx(g1 + 2);
#pragma unroll
        for (int j = 0; j < 16; j++) if (!(j & 2)) rxp(G2, X, Y, j, j | 2);
        GX G3 = load_gx(g1 + 3);
#pragma unroll
        for (int j = 0; j < 16; j += 2) { // last rotation + diagonal + store
            rxp(G3, X, Y, j, j | 1);
            diagp(d1, X, Y, j); diagp(d1, X, Y, j | 1);
            ulonglong2 v0; v0.x = X[j];     v0.y = Y[j];
            st[baseA + (tau4(j) << 8)] = v0;
            ulonglong2 v1; v1.x = X[j | 1]; v1.y = Y[j | 1];
            st[baseA + (tau4(j | 1) << 8)] = v1;
        }
    }
    __syncthreads();

    do_pass<1, 0>(st, g1 + 4, d1 + 16, baseB, baseBs, whigh, wk, 0, pacc); __syncthreads();
    do_pass<2, 0>(st, g1 + 8, d1 + 32, baseC, baseC,  whigh, wk, 0, pacc); __syncthreads();

    // ======== Layer 2 ========
    do_pass<0, 0>(st, g2,     d2,      baseA2, baseA,  whigh, wk, 0, pacc); __syncthreads();
    do_pass<1, 0>(st, g2 + 4, d2 + 16, baseB,  baseBs, whigh, wk, 0, pacc); __syncthreads();
    do_pass<2, 0>(st, g2 + 8, d2 + 32, baseC,  baseC,  whigh, wk, 0, pacc); __syncthreads();

    // ======== Layer 3 (tangent RX, scale deferred to alpha3^2) ========
    do_pass<0, 1>(st, g3,     nullptr, baseA2, baseA,  whigh, wk, 0, pacc); __syncthreads();
    do_pass<1, 1>(st, g3 + 4, nullptr, baseB,  baseBs, whigh, wk, 0, pacc); __syncthreads();
    do_pass<2, 2>(st, g3 + 8, nullptr, baseC,  baseC,  whigh, wk, wkxor, pacc);

    // ---- reduce both samples; apply deferred layer-3 scale ----
    float p0 = pacc[0], p1 = pacc[1];
#pragma unroll
    for (int o = 16; o; o >>= 1) {
        p0 += __shfl_xor_sync(0xFFFFFFFFu, p0, o);
        p1 += __shfl_xor_sync(0xFFFFFFFFu, p1, o);
    }
    if ((t & 31) == 0) red[t >> 5] = make_float2(p0, p1);
    __syncthreads();
    if (t < 2) {
        float s = 0.f;
#pragma unroll
        for (int w = 0; w < 8; w++) s += (t == 0) ? red[w].x : red[w].y;
        out[2 * b + t] = s * a3[0] + head_b[0];
    }
}

extern "C" void kernel_launch(void* const* d_in, const int* in_sizes, int n_in,
                              void* d_out, int out_size)
{
    const float* inputs = (const float*)d_in[0];
    const float* params = (const float*)d_in[1];
    const float* head_w = (const float*)d_in[2];
    const float* head_b = (const float*)d_in[3];
    float* out = (float*)d_out;

    cudaFuncSetAttribute(qsim6_kernel, cudaFuncAttributeMaxDynamicSharedMemorySize, SMEM_BYTES);
    int B2 = out_size / 2;   // two samples per block
    qsim6_kernel<<<B2, 256, SMEM_BYTES>>>(inputs, params, head_w, head_b, out);
}

// round 11
// speedup vs baseline: 1.2426x; 1.0358x over previous
#include <cuda_runtime.h>

// QuantumRegression: 12-wire state-vector sim, two samples per block packed
// into f32x2 lanes. State = 4096 x ulonglong2 (X=f32x2, Y=f32x2) = 64KB in
// shared, storage index sw(e) = e ^ ((e>>4)&7) (conflict-free for all pass
// layouts at 16B granularity, affine-in-k addressing per pass).  [R7 maps]
//
// Structure (compute passes identical to the verified R10 kernel):
//  - Layer 0 folded into closed-form product-state init (prefix parity).
//  - Layers 1..3: 3 passes of 4 rotated wires; CNOT(3,4) folded into pass-B
//    store base, CNOT(7,8) deferred into next pass-A load base (conjugated).
//  - TANGENT-FORM rotations (4 f32x2 FMA per pair); dropped cosines folded
//    into the deferred-RZ diagonal tables (L1,L2) / alpha3^2 scalar (L3).
//  - <Z> @ head_w measurement fused into the final pass.
//
// NEW this round: all batch-shared constants (tangent gates, diag tables,
// wk, alpha3^2, layer-0 param trig) are computed ONCE by a tiny pre-kernel
// into __device__ globals; the main kernel's setup becomes pipelined
// LDG->STS copies instead of per-block MUFU dependency chains, shrinking
// the barrier-fenced serial head that idles the smem crossbar.

typedef unsigned long long u64;

#define NW 12

// ---- batch-shared constant staging (written by qsetup_kernel) ----
__device__ ulonglong2 g_gx[36];      // tangent gates (tn, -tn) layers 1..3
__device__ ulonglong2 g_dtab[96];    // diag*prod(c) tables, layers 1..2
__device__ float      g_wk[16];      // measurement weights wires 8..11
__device__ float      g_a3;          // layer-3 prod(c)^2
__device__ float4     g_l0[12];      // per-wire layer-0: c0, s0, cos(th), sin(th)

// ---- packed f32x2 helpers ----
static __device__ __forceinline__ u64 pack2(float lo, float hi) {
    u64 r; asm("mov.b64 %0, {%1, %2};" : "=l"(r) : "f"(lo), "f"(hi)); return r;
}
static __device__ __forceinline__ float2 unpack2(u64 v) {
    float2 r; asm("mov.b64 {%0, %1}, %2;" : "=f"(r.x), "=f"(r.y) : "l"(v)); return r;
}
static __device__ __forceinline__ u64 dup2(float v) { return pack2(v, v); }
static __device__ __forceinline__ u64 fma2(u64 a, u64 b, u64 c) {
    u64 d; asm("fma.rn.f32x2 %0, %1, %2, %3;" : "=l"(d) : "l"(a), "l"(b), "l"(c)); return d;
}
static __device__ __forceinline__ u64 mul2(u64 a, u64 b) {
    u64 d; asm("mul.rn.f32x2 %0, %1, %2;" : "=l"(d) : "l"(a), "l"(b)); return d;
}
static __device__ __forceinline__ u64 neg2(u64 a) { return a ^ 0x8000000080000000ULL; }

// staircase CNOT permutation on 4 bits (GF2-linear)
__device__ __host__ __forceinline__ constexpr int tau4(int k) {
    int b3 = (k >> 3) & 1;
    int b2 = ((k >> 2) & 1) ^ b3;
    int b1 = ((k >> 1) & 1) ^ b2;
    int b0 = (k & 1) ^ b1;
    return (b3 << 3) | (b2 << 2) | (b1 << 1) | b0;
}

// ---- shared memory layout (bytes) ----
#define SM_ST   0        // ulonglong2 st[4096]            : 65536
#define SM_G    65536    // ulonglong2 gx[3*12] (tn,-tn)   : 576
#define SM_D    66112    // ulonglong2 dtab[2*3*16]        : 1536
#define SM_V    67648    // ulonglong2 v[12][2]            : 384
#define SM_F    68032    // ulonglong2 F[16]               : 256
#define SM_HW   68288    // float hw[12]                   : 48
#define SM_WK   68336    // float wk[16]                   : 64
#define SM_RED  68400    // float2 red[8]                  : 64
#define SM_A3   68464    // float alpha3sq                 : 4
#define SMEM_BYTES 68480

// ---- tangent-form RX gate bundle: one LDS.128 ----
struct GX { u64 tn, ntn; };
static __device__ __forceinline__ GX load_gx(const ulonglong2* __restrict__ g) {
    GX r; ulonglong2 p = g[0]; r.tn = p.x; r.ntn = p.y; return r;
}

// tangent-form RX rotation on pair (i0, i1): 4 FMAs (scale c deferred)
static __device__ __forceinline__ void rxp(const GX& G, u64* X, u64* Y, int i0, int i1) {
    u64 X0 = X[i0], Y0 = Y[i0], X1 = X[i1], Y1 = Y[i1];
    X[i0] = fma2(G.tn, Y1, X0);
    Y[i0] = fma2(G.ntn, X1, Y0);
    X[i1] = fma2(G.tn, Y0, X1);
    Y[i1] = fma2(G.ntn, X0, Y1);
}

// apply window diagonal D[k] (includes window prod(c); batch-shared)
static __device__ __forceinline__ void diagp(const ulonglong2* __restrict__ dt,
                                             u64* X, u64* Y, int k) {
    ulonglong2 d = dt[k];
    u64 nx = fma2(d.x, X[k], neg2(mul2(d.y, Y[k])));
    u64 ny = fma2(d.x, Y[k], mul2(d.y, X[k]));
    X[k] = nx; Y[k] = ny;
}

// Per-pass element address masks (applied to swizzled storage index).
template<int P>
__device__ __forceinline__ int addr_of(int base, int k) {
    if (P == 0)      return base + (k << 8);                  // immediate offsets
    else if (P == 1) return base ^ ((k << 4) | (k & 7));      // compile-time XOR mask
    else             return base ^ k;                         // compile-time XOR mask
}

// One pass: 4 tangent-RX rotations, then per MODE:
//  MODE 0: window diagonal dt + CNOT-permuted store   (layers 1,2)
//  MODE 1: CNOT-permuted store, no diagonal           (layer 3, passes A,B)
//  MODE 2: fused measurement, no diagonal             (layer 3, pass C)
template<int P, int MODE>
__device__ __forceinline__ void do_pass(ulonglong2* __restrict__ st,
                                        const ulonglong2* __restrict__ g,
                                        const ulonglong2* __restrict__ dt,
                                        int loadBase, int storeBase,
                                        float whigh, const float* __restrict__ wk,
                                        int wkxor, float* pacc)
{
    u64 X[16], Y[16];
    GX G0 = load_gx(g);
#pragma unroll
    for (int j = 0; j < 8; j++) {              // load pair + first rotation
        ulonglong2 a = st[addr_of<P>(loadBase, j)];
        ulonglong2 b = st[addr_of<P>(loadBase, j | 8)];
        X[j] = a.x; Y[j] = a.y; X[j | 8] = b.x; Y[j | 8] = b.y;
        rxp(G0, X, Y, j, j | 8);
    }
    GX G1 = load_gx(g + 1);
#pragma unroll
    for (int j = 0; j < 16; j++) if (!(j & 4)) rxp(G1, X, Y, j, j | 4);
    GX G2 = load_gx(g + 2);
#pragma unroll
    for (int j = 0; j < 16; j++) if (!(j & 2)) rxp(G2, X, Y, j, j | 2);
    GX G3 = load_gx(g + 3);
#pragma unroll
    for (int j = 0; j < 16; j += 2) {          // last rotation + epilogue
        rxp(G3, X, Y, j, j | 1);
        if constexpr (MODE == 2) {             // fused measurement
            int i0 = tau4(j) ^ wkxor;
            float wl = whigh + wk[i0];
            u64 U = fma2(X[j], X[j], mul2(Y[j], Y[j]));
            float2 u = unpack2(U);
            pacc[0] = fmaf(u.x, wl, pacc[0]);
            pacc[1] = fmaf(u.y, wl, pacc[1]);
            int i1 = tau4(j | 1) ^ wkxor;
            wl = whigh + wk[i1];
            U = fma2(X[j | 1], X[j | 1], mul2(Y[j | 1], Y[j | 1]));
            u = unpack2(U);
            pacc[0] = fmaf(u.x, wl, pacc[0]);
            pacc[1] = fmaf(u.y, wl, pacc[1]);
        } else {
            if constexpr (MODE == 0) { diagp(dt, X, Y, j); diagp(dt, X, Y, j | 1); }
            ulonglong2 v0; v0.x = X[j];     v0.y = Y[j];
            st[addr_of<P>(storeBase, tau4(j))] = v0;
            ulonglong2 v1; v1.x = X[j | 1]; v1.y = Y[j | 1];
            st[addr_of<P>(storeBase, tau4(j | 1))] = v1;
        }
    }
}

// ---- pre-kernel: batch-shared constants, one block ----
__global__ void qsetup_kernel(const float* __restrict__ params,
                              const float* __restrict__ head_w)
{
    int t = threadIdx.x;
    if (t < 36) {                      // tangent coeffs: layer 1+t/12, wire t%12
        float th = params[12 + t];
        float c, s; sincosf(0.5f * th, &s, &c);
        float tn = s / c;
        ulonglong2 e; e.x = dup2(tn); e.y = dup2(-tn);
        g_gx[t] = e;
    }
    if (t == 40) {                     // layer-3 scalar: prod(c)^2
        float prod = 1.f;
#pragma unroll
        for (int w = 0; w < NW; w++) prod *= cosf(0.5f * params[36 + w]);
        g_a3 = prod * prod;
    }
    if (t >= 64 && t < 160) {          // diag tables: prod(c) * e^{i sum th_w bit_w}
        int i = t - 64;                // layer = i/48 (0->L1), window = (i%48)/16, m = i&15
        int l = i / 48, p = (i % 48) / 16, m = i & 15;
        const float* th = params + (l + 1) * NW + 4 * p;
        float phi = 0.f, cprod = 1.f;
#pragma unroll
        for (int q = 0; q < 4; q++) {
            if ((m >> (3 - q)) & 1) phi += th[q];
            cprod *= cosf(0.5f * th[q]);
        }
        float cp, sp; sincosf(phi, &sp, &cp);
        ulonglong2 e; e.x = dup2(cprod * cp); e.y = dup2(cprod * sp);
        g_dtab[i] = e;
    }
    if (t >= 160 && t < 176) {         // measurement weights for wires 8..11
        int m = t - 160;
        float w8 = head_w[8], w9 = head_w[9], w10 = head_w[10], w11 = head_w[11];
        g_wk[m] = ((m & 8) ? -w8 : w8) + ((m & 4) ? -w9 : w9)
                + ((m & 2) ? -w10 : w10) + ((m & 1) ? -w11 : w11);
    }
    if (t >= 176 && t < 188) {         // layer-0 per-wire param trig
        int w = t - 176;
        float c0, s0; sincosf(0.5f * params[w], &s0, &c0);
        g_l0[w] = make_float4(c0, s0, c0 * c0 - s0 * s0, 2.f * s0 * c0);
    }
}

__global__ void __launch_bounds__(256, 2)
qsim7_kernel(const float* __restrict__ inputs,
             const float* __restrict__ head_w,
             const float* __restrict__ head_b,
             float* __restrict__ out)
{
    extern __shared__ char sm[];
    ulonglong2* st   = (ulonglong2*)(sm + SM_ST);
    ulonglong2* gx   = (ulonglong2*)(sm + SM_G);
    ulonglong2* dtab = (ulonglong2*)(sm + SM_D);
    ulonglong2* vtab = (ulonglong2*)(sm + SM_V);
    ulonglong2* Ftab = (ulonglong2*)(sm + SM_F);
    float* hw  = (float*)(sm + SM_HW);
    float* wk  = (float*)(sm + SM_WK);
    float2* red = (float2*)(sm + SM_RED);
    float* a3  = (float*)(sm + SM_A3);

    const int b = blockIdx.x;
    const int t = threadIdx.x;

    // ---- phase 1: stage batch-shared constants (LDG->STS) + per-sample trig ----
    if (t < 36) gx[t] = g_gx[t];
    if (t >= 64 && t < 160) dtab[t - 64] = g_dtab[t - 64];
    if (t >= 160 && t < 176) wk[t - 160] = g_wk[t - 160];
    if (t == 176) a3[0] = g_a3;
    if (t < NW) {                      // layer-0 per-wire 2-vectors (both samples)
        int w = t;
        float4 l0 = g_l0[w];
        float c0 = l0.x, s0 = l0.y, cn = l0.z, sn = l0.w;
        float v0x[2], v0y[2], v1x[2], v1y[2];
#pragma unroll
        for (int j = 0; j < 2; j++) {
            float cy, sy; sincosf(0.5f * inputs[(2 * b + j) * NW + w], &sy, &cy);
            v0x[j] = c0 * cy;  v0y[j] = -s0 * sy;
            float zx = c0 * sy, zy = -s0 * cy;           // z = -i s cy + c sy
            v1x[j] = cn * zx - sn * zy;                   // e^{i th} * z
            v1y[j] = sn * zx + cn * zy;
        }
        ulonglong2 e0; e0.x = pack2(v0x[0], v0x[1]); e0.y = pack2(v0y[0], v0y[1]);
        ulonglong2 e1; e1.x = pack2(v1x[0], v1x[1]); e1.y = pack2(v1y[0], v1y[1]);
        vtab[(w << 1) | 0] = e0;
        vtab[(w << 1) | 1] = e1;
        hw[w] = head_w[w];
    }
    __syncthreads();

    // ---- phase 2: F table (wires 0..3 staircase products, per sample-pair) ----
    if (t < 16) {
        int c0 = (t >> 3) & 1, c1 = (t >> 2) & 1, c2 = (t >> 1) & 1, c3 = t & 1;
        int b0 = c0, b1 = c1 ^ c0, b2 = c2 ^ c1, b3 = c3 ^ c2;
        ulonglong2 a = vtab[0 | b0];
        u64 PX = a.x, PY = a.y;
        int bb[3] = {b1, b2, b3};
#pragma unroll
        for (int w = 1; w <= 3; w++) {
            ulonglong2 q = vtab[(w << 1) | bb[w - 1]];
            u64 nx = fma2(PX, q.x, neg2(mul2(PY, q.y)));
            u64 ny = fma2(PX, q.y, mul2(PY, q.x));
            PX = nx; PY = ny;
        }
        ulonglong2 f; f.x = PX; f.y = PY; Ftab[t] = f;
    }

    // per-thread bases (R7 maps, verified)
    const int baseA  = t ^ ((t >> 4) & 7);              // pass-A canonical base
    const int tA2    = t ^ (((t >> 4) & 1) * 0xF);      // conjugated C78 deferral
    const int baseA2 = tA2 ^ ((tA2 >> 4) & 7);          // pass-A load base (L2,L3)
    const int baseB  = ((t >> 4) << 8) | (t & 15);
    const int baseBs = baseB ^ (((t >> 4) & 1) ? 0xF7 : 0);  // CNOT(3,4) fold
    const int baseC  = (t << 4) | (t & 7);
    const int wkxor  = (t & 1) ? 0xF : 0;               // CNOT(7,8) fold at measure

    // measurement weight for wires 0..7 (t bits 7..0, wire i <-> t bit 7-i)
    float whigh = 0.f;
#pragma unroll
    for (int m = 0; m < 8; m++) {
        float w = hw[7 - m];
        whigh += ((t >> m) & 1) ? -w : w;
    }
    __syncthreads();

    float pacc[2] = {0.f, 0.f};
    const ulonglong2* g1 = gx;            // layer 1 (12 gates)
    const ulonglong2* g2 = gx + 12;       // layer 2
    const ulonglong2* g3 = gx + 24;       // layer 3
    const ulonglong2* d1 = dtab;          // layer-1 diagonals (3 windows x 16)
    const ulonglong2* d2 = dtab + 48;     // layer-2 diagonals

    // ======== Layer 1, pass A: closed-form init + tan-rx chain + diag ====
    {
        u64 X[16], Y[16];
        int u = t ^ (t >> 1);             // u bit (11-w) = b_w for wires 5..11
        ulonglong2 p5 = vtab[(5 << 1) | ((u >> 6) & 1)];
        u64 PX = p5.x, PY = p5.y;
#pragma unroll
        for (int w = 6; w <= 11; w++) {
            ulonglong2 q = vtab[(w << 1) | ((u >> (11 - w)) & 1)];
            u64 nx = fma2(PX, q.x, neg2(mul2(PY, q.y)));
            u64 ny = fma2(PX, q.y, mul2(PY, q.x));
            PX = nx; PY = ny;
        }
        int t7 = (t >> 7) & 1;
        ulonglong2 q0 = vtab[(4 << 1) | t7];
        ulonglong2 q1 = vtab[(4 << 1) | (t7 ^ 1)];
        u64 R0X = fma2(PX, q0.x, neg2(mul2(PY, q0.y)));
        u64 R0Y = fma2(PX, q0.y, mul2(PY, q0.x));
        u64 R1X = fma2(PX, q1.x, neg2(mul2(PY, q1.y)));
        u64 R1Y = fma2(PX, q1.y, mul2(PY, q1.x));
        GX G0 = load_gx(g1);
#pragma unroll
        for (int j = 0; j < 8; j++) {     // build pair (j, j|8) then rotate it
            ulonglong2 Fk0 = Ftab[j];
            u64 QX = (j & 1) ? R1X : R0X;
            u64 QY = (j & 1) ? R1Y : R0Y;
            X[j] = fma2(Fk0.x, QX, neg2(mul2(Fk0.y, QY)));
            Y[j] = fma2(Fk0.x, QY, mul2(Fk0.y, QX));
            ulonglong2 Fk1 = Ftab[j | 8];
            X[j | 8] = fma2(Fk1.x, QX, neg2(mul2(Fk1.y, QY)));
            Y[j | 8] = fma2(Fk1.x, QY, mul2(Fk1.y, QX));
            rxp(G0, X, Y, j, j | 8);
        }
        GX G1 = load_gx(g1 + 1);
#pragma unroll
        for (int j = 0; j < 16; j++) if (!(j & 4)) rxp(G1, X, Y, j, j | 4);
        GX G2 = load_gx(g1 + 2);
#pragma unroll
        for (int j = 0; j < 16; j++) if (!(j & 2)) rxp(G2, X, Y, j, j | 2);
        GX G3 = load_gx(g1 + 3);
#pragma unroll
        for (int j = 0; j < 16; j += 2) { // last rotation + diagonal + store
            rxp(G3, X, Y, j, j | 1);
            diagp(d1, X, Y, j); diagp(d1, X, Y, j | 1);
            ulonglong2 v0; v0.x = X[j];     v0.y = Y[j];
            st[baseA + (tau4(j) << 8)] = v0;
            ulonglong2 v1; v1.x = X[j | 1]; v1.y = Y[j | 1];
            st[baseA + (tau4(j | 1) << 8)] = v1;
        }
    }
    __syncthreads();

    do_pass<1, 0>(st, g1 + 4, d1 + 16, baseB, baseBs, whigh, wk, 0, pacc); __syncthreads();
    do_pass<2, 0>(st, g1 + 8, d1 + 32, baseC, baseC,  whigh, wk, 0, pacc); __syncthreads();

    // ======== Layer 2 ========
    do_pass<0, 0>(st, g2,     d2,      baseA2, baseA,  whigh, wk, 0, pacc); __syncthreads();
    do_pass<1, 0>(st, g2 + 4, d2 + 16, baseB,  baseBs, whigh, wk, 0, pacc); __syncthreads();
    do_pass<2, 0>(st, g2 + 8, d2 + 32, baseC,  baseC,  whigh, wk, 0, pacc); __syncthreads();

    // ======== Layer 3 (tangent RX, scale deferred to alpha3^2) ========
    do_pass<0, 1>(st, g3,     nullptr, baseA2, baseA,  whigh, wk, 0, pacc); __syncthreads();
    do_pass<1, 1>(st, g3 + 4, nullptr, baseB,  baseBs, whigh, wk, 0, pacc); __syncthreads();
    do_pass<2, 2>(st, g3 + 8, nullptr, baseC,  baseC,  whigh, wk, wkxor, pacc);

    // ---- reduce both samples; apply deferred layer-3 scale ----
    float p0 = pacc[0], p1 = pacc[1];
#pragma unroll
    for (int o = 16; o; o >>= 1) {
        p0 += __shfl_xor_sync(0xFFFFFFFFu, p0, o);
        p1 += __shfl_xor_sync(0xFFFFFFFFu, p1, o);
    }
    if ((t & 31) == 0) red[t >> 5] = make_float2(p0, p1);
    __syncthreads();
    if (t < 2) {
        float s = 0.f;
#pragma unroll
        for (int w = 0; w < 8; w++) s += (t == 0) ? red[w].x : red[w].y;
        out[2 * b + t] = s * a3[0] + head_b[0];
    }
}

extern "C" void kernel_launch(void* const* d_in, const int* in_sizes, int n_in,
                              void* d_out, int out_size)
{
    const float* inputs = (const float*)d_in[0];
    const float* params = (const float*)d_in[1];
    const float* head_w = (const float*)d_in[2];
    const float* head_b = (const float*)d_in[3];
    float* out = (float*)d_out;

    cudaFuncSetAttribute(qsim7_kernel, cudaFuncAttributeMaxDynamicSharedMemorySize, SMEM_BYTES);
    qsetup_kernel<<<1, 192>>>(params, head_w);           // batch-shared constants
    int B2 = out_size / 2;                               // two samples per block
    qsim7_kernel<<<B2, 256, SMEM_BYTES>>>(inputs, head_w, head_b, out);
}